// round 6
// baseline (speedup 1.0000x reference)
#include <cuda_runtime.h>
#include <math.h>
#include <stdint.h>

#define H_DIM 1024
#define SB 104448
#define OUT_CH 904
#define NMIX 50
#define FULLMASK 0xFFFFFFFFu

__device__ __forceinline__ float fadd_s(float a, float b) { return __fadd_rn(a, b); }

// ---------------- Threefry2x32 (JAX partitionable) ----------------
struct U2 { unsigned a, b; };
__host__ __device__ constexpr unsigned rotl32(unsigned x, int r) {
  return (x << r) | (x >> (32 - r));
}
__host__ __device__ constexpr U2 threefry2x32(unsigned k0, unsigned k1,
                                              unsigned c0, unsigned c1) {
  unsigned ks[3] = {k0, k1, k0 ^ k1 ^ 0x1BD11BDAu};
  unsigned x0 = c0 + k0, x1 = c1 + k1;
  const int rot[2][4] = {{13, 15, 26, 6}, {17, 29, 16, 24}};
#pragma unroll
  for (int g = 0; g < 5; ++g) {
    const int* r = rot[g & 1];
#pragma unroll
    for (int i = 0; i < 4; ++i) { x0 += x1; x1 = rotl32(x1, r[i]); x1 ^= x0; }
    x0 += ks[(g + 1) % 3];
    x1 += ks[(g + 2) % 3] + (unsigned)(g + 1);
  }
  return U2{x0, x1};
}
constexpr unsigned KCMD0 = threefry2x32(0u, 42u, 0u, 0u).a;
constexpr unsigned KCMD1 = threefry2x32(0u, 42u, 0u, 0u).b;
constexpr unsigned KMIX0 = threefry2x32(0u, 42u, 0u, 1u).a;
constexpr unsigned KMIX1 = threefry2x32(0u, 42u, 0u, 1u).b;
constexpr unsigned KG0   = threefry2x32(0u, 42u, 0u, 2u).a;
constexpr unsigned KG1   = threefry2x32(0u, 42u, 0u, 2u).b;

__device__ __forceinline__ float bits_to_f01(unsigned k0, unsigned k1, unsigned idx) {
  U2 o = threefry2x32(k0, k1, 0u, idx);
  return __uint_as_float((((o.a ^ o.b) >> 9) | 0x3f800000u)) - 1.0f;
}
__device__ __forceinline__ float gumbel_at(unsigned k0, unsigned k1, unsigned idx) {
  float u = fmaxf(bits_to_f01(k0, k1, idx), 1.17549435e-38f);
  return -logf(-logf(u));
}
__device__ __forceinline__ float normal_at(unsigned k0, unsigned k1, unsigned idx) {
  const float lo = __int_as_float(0xBF7FFFFF);  // nextafterf(-1,0)
  float u = fmaxf(__fadd_rn(__fmul_rn(bits_to_f01(k0, k1, idx), 2.0f), lo), lo);
  return __fmul_rn(1.41421356237f, erfinvf(u));
}

__device__ float g_ret[(size_t)SB * OUT_CH];

// ---------------- GEMM: Eigen kc=320 panel chains ----------------
// evaluateProductBlockingSizesHeuristic caps k_cache at 320 for any L1>=20KB.
// Per element: ascending-k FMA chain within panels [0,320),[320,640),
// [640,960),[960,1024); totals folded ascending (C=p0; C+=p1; ...).
#define BM 128
#define BN 64
#define BK 16

__global__ void __launch_bounds__(128) gemm_kernel(
    const float* __restrict__ A, const float* __restrict__ W,
    const float* __restrict__ bias) {
  __shared__ float As[BK][BM + 4];
  __shared__ float Ws[BK][BN + 4];
  const int bm = blockIdx.x * BM, bn = blockIdx.y * BN;
  const int tid = (int)threadIdx.x;
  const int lr = tid >> 2;        // 0..31
  const int lk = (tid & 3) << 2;  // 0,4,8,12
  const int ty = tid >> 3, tx = tid & 7;

  float acc[8][8], tot[8][8];
#pragma unroll
  for (int i = 0; i < 8; ++i)
#pragma unroll
    for (int j = 0; j < 8; ++j) { acc[i][j] = 0.0f; tot[i][j] = 0.0f; }

  for (int k0 = 0; k0 < H_DIM; k0 += BK) {
#pragma unroll
    for (int i = 0; i < 4; ++i) {
      int m = lr + 32 * i;
      float4 v = *reinterpret_cast<const float4*>(
          A + (size_t)(bm + m) * H_DIM + k0 + lk);
      As[lk + 0][m] = v.x; As[lk + 1][m] = v.y;
      As[lk + 2][m] = v.z; As[lk + 3][m] = v.w;
    }
#pragma unroll
    for (int i = 0; i < 2; ++i) {
      int n = lr + 32 * i;
      int ng = bn + n;
      float4 v = make_float4(0.f, 0.f, 0.f, 0.f);
      if (ng < OUT_CH)
        v = *reinterpret_cast<const float4*>(W + (size_t)ng * H_DIM + k0 + lk);
      Ws[lk + 0][n] = v.x; Ws[lk + 1][n] = v.y;
      Ws[lk + 2][n] = v.z; Ws[lk + 3][n] = v.w;
    }
    __syncthreads();

#pragma unroll
    for (int kk = 0; kk < BK; ++kk) {
      float af[8], bf[8];
      *reinterpret_cast<float4*>(&af[0]) = *reinterpret_cast<const float4*>(&As[kk][ty * 8]);
      *reinterpret_cast<float4*>(&af[4]) = *reinterpret_cast<const float4*>(&As[kk][ty * 8 + 4]);
      *reinterpret_cast<float4*>(&bf[0]) = *reinterpret_cast<const float4*>(&Ws[kk][tx * 8]);
      *reinterpret_cast<float4*>(&bf[4]) = *reinterpret_cast<const float4*>(&Ws[kk][tx * 8 + 4]);
#pragma unroll
      for (int i = 0; i < 8; ++i)
#pragma unroll
        for (int j = 0; j < 8; ++j) acc[i][j] = fmaf(af[i], bf[j], acc[i][j]);
    }

    int ke = k0 + BK;  // Eigen kc=320 fold points: 320, 640, 960, 1024
    if ((ke % 320) == 0 || ke == H_DIM) {
#pragma unroll
      for (int i = 0; i < 8; ++i)
#pragma unroll
        for (int j = 0; j < 8; ++j) { tot[i][j] = fadd_s(tot[i][j], acc[i][j]); acc[i][j] = 0.0f; }
    }
    __syncthreads();
  }

#pragma unroll
  for (int i = 0; i < 8; ++i) {
    float* o = g_ret + (size_t)(bm + ty * 8 + i) * OUT_CH;
#pragma unroll
    for (int j = 0; j < 8; ++j) {
      int n = bn + tx * 8 + j;
      if (n < OUT_CH) o[n] = fadd_s(tot[i][j], __ldg(&bias[n]));
    }
  }
}

// ---------------- Sampling: one warp per (s,b) row ----------------
__global__ void __launch_bounds__(256) sample_kernel(float* __restrict__ out) {
  int gw = (int)((blockIdx.x * blockDim.x + threadIdx.x) >> 5);
  int lane = (int)(threadIdx.x & 31);
  if (gw >= SB) return;
  const float* row = g_ret + (size_t)gw * OUT_CH;

  // command: argmax(x/tau + gumbel) over 4
  float v = __int_as_float(0xFF800000);
  int vi = lane;
  if (lane < 4)
    v = __fadd_rn(__fdiv_rn(row[lane], 1e-4f),
                  gumbel_at(KCMD0, KCMD1, (unsigned)(gw * 4 + lane)));
#pragma unroll
  for (int off = 16; off > 0; off >>= 1) {
    float vo = __shfl_xor_sync(FULLMASK, v, off);
    int io = __shfl_xor_sync(FULLMASK, vi, off);
    if (vo > v || (vo == v && io < vi)) { v = vo; vi = io; }
  }
  if (lane < 4) out[(size_t)gw * 10 + lane] = (lane == vi) ? 1.0f : 0.0f;

  for (int j = 0; j < 6; ++j) {
    const float* p = row + 4 + j * 150;
    const int t1 = lane + 32;
    const bool has1 = (t1 < NMIX);
    float x0 = p[lane];
    float x1 = has1 ? p[t1] : __int_as_float(0xFF800000);

    float mx = fmaxf(x0, x1);
#pragma unroll
    for (int off = 16; off > 0; off >>= 1)
      mx = fmaxf(mx, __shfl_xor_sync(FULLMASK, mx, off));
    float s = expf(x0 - mx) + (has1 ? expf(x1 - mx) : 0.0f);
#pragma unroll
    for (int off = 16; off > 0; off >>= 1)
      s += __shfl_xor_sync(FULLMASK, s, off);
    float lse = logf(s) + mx;

    float y0 = __fdiv_rn(__fadd_rn(x0, -lse), 1e-4f);
    float y1 = has1 ? __fdiv_rn(__fadd_rn(x1, -lse), 1e-4f) : __int_as_float(0xFF800000);
    float ym = fmaxf(y0, y1);
#pragma unroll
    for (int off = 16; off > 0; off >>= 1)
      ym = fmaxf(ym, __shfl_xor_sync(FULLMASK, ym, off));

    // gumbel spread is <= 20.412 < 20.45: only candidates in window can win
    float thr = ym - 20.45f;
    unsigned m0 = __ballot_sync(FULLMASK, y0 >= thr);
    unsigned m1 = __ballot_sync(FULLMASK, has1 && (y1 >= thr));
    int mixidx;
    if (__popc(m0) + __popc(m1) == 1) {
      mixidx = m0 ? (__ffs(m0) - 1) : (__ffs(m1) + 31);
    } else {
      unsigned base = (unsigned)(gw * 6 + j) * 50u;
      float z = __int_as_float(0xFF800000);
      int zi = 64;
      if (y0 >= thr) { z = __fadd_rn(y0, gumbel_at(KMIX0, KMIX1, base + (unsigned)lane)); zi = lane; }
      if (has1 && y1 >= thr) {
        float z1 = __fadd_rn(y1, gumbel_at(KMIX0, KMIX1, base + (unsigned)t1));
        if (z1 > z) { z = z1; zi = t1; }
      }
#pragma unroll
      for (int off = 16; off > 0; off >>= 1) {
        float zo = __shfl_xor_sync(FULLMASK, z, off);
        int io = __shfl_xor_sync(FULLMASK, zi, off);
        if (zo > z || (zo == z && io < zi)) { z = zo; zi = io; }
      }
      mixidx = zi;
    }

    if (lane == 0) {
      float nrm = normal_at(KG0, KG1, (unsigned)(gw * 6 + j));
      float noise = __fmul_rn(nrm, 0.01f);
      out[(size_t)gw * 10 + 4 + j] =
          __fadd_rn(p[50 + mixidx], __fmul_rn(expf(p[100 + mixidx]), noise));
    }
  }
}

extern "C" void kernel_launch(void* const* d_in, const int* in_sizes, int n_in,
                              void* d_out, int out_size) {
  const float* A = (const float*)d_in[0];
  const float* W = (const float*)d_in[1];
  const float* bias = (const float*)d_in[2];
  float* out = (float*)d_out;

  dim3 ggrid(SB / BM, (OUT_CH + BN - 1) / BN);
  gemm_kernel<<<ggrid, 128>>>(A, W, bias);
  sample_kernel<<<SB / 8, 256>>>(out);
}

// round 7
// speedup vs baseline: 1.1235x; 1.1235x over previous
#include <cuda_runtime.h>
#include <math.h>
#include <stdint.h>

#define H_DIM 1024
#define SB 104448
#define OUT_CH 904
#define NMIX 50
#define FULLMASK 0xFFFFFFFFu

__device__ __forceinline__ float fadd_s(float a, float b) { return __fadd_rn(a, b); }

// ---------------- Threefry2x32 (JAX partitionable) ----------------
struct U2 { unsigned a, b; };
__host__ __device__ constexpr unsigned rotl32(unsigned x, int r) {
  return (x << r) | (x >> (32 - r));
}
__host__ __device__ constexpr U2 threefry2x32(unsigned k0, unsigned k1,
                                              unsigned c0, unsigned c1) {
  unsigned ks[3] = {k0, k1, k0 ^ k1 ^ 0x1BD11BDAu};
  unsigned x0 = c0 + k0, x1 = c1 + k1;
  const int rot[2][4] = {{13, 15, 26, 6}, {17, 29, 16, 24}};
#pragma unroll
  for (int g = 0; g < 5; ++g) {
    const int* r = rot[g & 1];
#pragma unroll
    for (int i = 0; i < 4; ++i) { x0 += x1; x1 = rotl32(x1, r[i]); x1 ^= x0; }
    x0 += ks[(g + 1) % 3];
    x1 += ks[(g + 2) % 3] + (unsigned)(g + 1);
  }
  return U2{x0, x1};
}
constexpr unsigned KCMD0 = threefry2x32(0u, 42u, 0u, 0u).a;
constexpr unsigned KCMD1 = threefry2x32(0u, 42u, 0u, 0u).b;
constexpr unsigned KMIX0 = threefry2x32(0u, 42u, 0u, 1u).a;
constexpr unsigned KMIX1 = threefry2x32(0u, 42u, 0u, 1u).b;
constexpr unsigned KG0   = threefry2x32(0u, 42u, 0u, 2u).a;
constexpr unsigned KG1   = threefry2x32(0u, 42u, 0u, 2u).b;

__device__ __forceinline__ float bits_to_f01(unsigned k0, unsigned k1, unsigned idx) {
  U2 o = threefry2x32(k0, k1, 0u, idx);
  return __uint_as_float((((o.a ^ o.b) >> 9) | 0x3f800000u)) - 1.0f;
}
__device__ __forceinline__ float gumbel_at(unsigned k0, unsigned k1, unsigned idx) {
  float u = fmaxf(bits_to_f01(k0, k1, idx), 1.17549435e-38f);
  return -logf(-logf(u));
}
__device__ __forceinline__ float normal_at(unsigned k0, unsigned k1, unsigned idx) {
  const float lo = __int_as_float(0xBF7FFFFF);  // nextafterf(-1,0)
  float u = fmaxf(__fadd_rn(__fmul_rn(bits_to_f01(k0, k1, idx), 2.0f), lo), lo);
  return __fmul_rn(1.41421356237f, erfinvf(u));
}

__device__ float g_ret[(size_t)SB * OUT_CH];

// ---------------- GEMM: Eigen kc=320 panel chains (LOCKED bits) ----------------
// Per element: ascending-k FMA chain within panels [0,320),[320,640),
// [640,960),[960,1024); totals folded ascending. IDENTICAL math to round 6.
// Perf changes only: double-buffered smem + register prefetch (1 sync/iter),
// grid transposed so bn varies fastest (A stays hot in L2, read once).
#define BM 128
#define BN 64
#define BK 16
#define KITERS (H_DIM / BK)  // 64

__global__ void __launch_bounds__(128) gemm_kernel(
    const float* __restrict__ A, const float* __restrict__ W,
    const float* __restrict__ bias) {
  __shared__ float As[2][BK][BM + 4];
  __shared__ float Ws[2][BK][BN + 4];

  const int bn = blockIdx.x * BN;   // fastest axis -> W + A super-row hot in L2
  const int bm = blockIdx.y * BM;
  const int tid = (int)threadIdx.x;
  const int lr = tid >> 2;          // 0..31
  const int lk = (tid & 3) << 2;    // 0,4,8,12
  const int ty = tid >> 3, tx = tid & 7;

  const float* Abase = A + (size_t)bm * H_DIM + lk;
  float4 pa[4];
  float4 pw[2];

  // prefetch helpers (global -> registers)
#define LOAD_GLOBAL(K0)                                                        \
  {                                                                            \
    _Pragma("unroll") for (int i = 0; i < 4; ++i) pa[i] =                      \
        *reinterpret_cast<const float4*>(Abase + (size_t)(lr + 32 * i) * H_DIM + (K0)); \
    _Pragma("unroll") for (int i = 0; i < 2; ++i) {                            \
      int ng = bn + lr + 32 * i;                                               \
      pw[i] = make_float4(0.f, 0.f, 0.f, 0.f);                                 \
      if (ng < OUT_CH)                                                         \
        pw[i] = *reinterpret_cast<const float4*>(W + (size_t)ng * H_DIM + (K0) + lk); \
    }                                                                          \
  }

#define STORE_SMEM(BUF)                                                        \
  {                                                                            \
    _Pragma("unroll") for (int i = 0; i < 4; ++i) {                            \
      int m = lr + 32 * i;                                                     \
      As[BUF][lk + 0][m] = pa[i].x; As[BUF][lk + 1][m] = pa[i].y;              \
      As[BUF][lk + 2][m] = pa[i].z; As[BUF][lk + 3][m] = pa[i].w;              \
    }                                                                          \
    _Pragma("unroll") for (int i = 0; i < 2; ++i) {                            \
      int n = lr + 32 * i;                                                     \
      Ws[BUF][lk + 0][n] = pw[i].x; Ws[BUF][lk + 1][n] = pw[i].y;              \
      Ws[BUF][lk + 2][n] = pw[i].z; Ws[BUF][lk + 3][n] = pw[i].w;              \
    }                                                                          \
  }

  float acc[8][8], tot[8][8];
#pragma unroll
  for (int i = 0; i < 8; ++i)
#pragma unroll
    for (int j = 0; j < 8; ++j) { acc[i][j] = 0.0f; tot[i][j] = 0.0f; }

  LOAD_GLOBAL(0)
  STORE_SMEM(0)
  __syncthreads();

  for (int it = 0; it < KITERS; ++it) {
    const int cur = it & 1;
    if (it + 1 < KITERS) LOAD_GLOBAL((it + 1) * BK)

#pragma unroll
    for (int kk = 0; kk < BK; ++kk) {
      float af[8], bf[8];
      *reinterpret_cast<float4*>(&af[0]) = *reinterpret_cast<const float4*>(&As[cur][kk][ty * 8]);
      *reinterpret_cast<float4*>(&af[4]) = *reinterpret_cast<const float4*>(&As[cur][kk][ty * 8 + 4]);
      *reinterpret_cast<float4*>(&bf[0]) = *reinterpret_cast<const float4*>(&Ws[cur][kk][tx * 8]);
      *reinterpret_cast<float4*>(&bf[4]) = *reinterpret_cast<const float4*>(&Ws[cur][kk][tx * 8 + 4]);
#pragma unroll
      for (int i = 0; i < 8; ++i)
#pragma unroll
        for (int j = 0; j < 8; ++j) acc[i][j] = fmaf(af[i], bf[j], acc[i][j]);
    }

    int ke = (it + 1) * BK;  // Eigen kc=320 fold points: 320, 640, 960, 1024
    if ((ke % 320) == 0 || ke == H_DIM) {
#pragma unroll
      for (int i = 0; i < 8; ++i)
#pragma unroll
        for (int j = 0; j < 8; ++j) { tot[i][j] = fadd_s(tot[i][j], acc[i][j]); acc[i][j] = 0.0f; }
    }

    if (it + 1 < KITERS) STORE_SMEM((it + 1) & 1)
    __syncthreads();
  }

#pragma unroll
  for (int i = 0; i < 8; ++i) {
    float* o = g_ret + (size_t)(bm + ty * 8 + i) * OUT_CH;
#pragma unroll
    for (int j = 0; j < 8; ++j) {
      int n = bn + tx * 8 + j;
      if (n < OUT_CH) o[n] = fadd_s(tot[i][j], __ldg(&bias[n]));
    }
  }
#undef LOAD_GLOBAL
#undef STORE_SMEM
}

// ---------------- Sampling: one warp per (s,b) row (unchanged) ----------------
__global__ void __launch_bounds__(256) sample_kernel(float* __restrict__ out) {
  int gw = (int)((blockIdx.x * blockDim.x + threadIdx.x) >> 5);
  int lane = (int)(threadIdx.x & 31);
  if (gw >= SB) return;
  const float* row = g_ret + (size_t)gw * OUT_CH;

  float v = __int_as_float(0xFF800000);
  int vi = lane;
  if (lane < 4)
    v = __fadd_rn(__fdiv_rn(row[lane], 1e-4f),
                  gumbel_at(KCMD0, KCMD1, (unsigned)(gw * 4 + lane)));
#pragma unroll
  for (int off = 16; off > 0; off >>= 1) {
    float vo = __shfl_xor_sync(FULLMASK, v, off);
    int io = __shfl_xor_sync(FULLMASK, vi, off);
    if (vo > v || (vo == v && io < vi)) { v = vo; vi = io; }
  }
  if (lane < 4) out[(size_t)gw * 10 + lane] = (lane == vi) ? 1.0f : 0.0f;

  for (int j = 0; j < 6; ++j) {
    const float* p = row + 4 + j * 150;
    const int t1 = lane + 32;
    const bool has1 = (t1 < NMIX);
    float x0 = p[lane];
    float x1 = has1 ? p[t1] : __int_as_float(0xFF800000);

    float mx = fmaxf(x0, x1);
#pragma unroll
    for (int off = 16; off > 0; off >>= 1)
      mx = fmaxf(mx, __shfl_xor_sync(FULLMASK, mx, off));
    float s = expf(x0 - mx) + (has1 ? expf(x1 - mx) : 0.0f);
#pragma unroll
    for (int off = 16; off > 0; off >>= 1)
      s += __shfl_xor_sync(FULLMASK, s, off);
    float lse = logf(s) + mx;

    float y0 = __fdiv_rn(__fadd_rn(x0, -lse), 1e-4f);
    float y1 = has1 ? __fdiv_rn(__fadd_rn(x1, -lse), 1e-4f) : __int_as_float(0xFF800000);
    float ym = fmaxf(y0, y1);
#pragma unroll
    for (int off = 16; off > 0; off >>= 1)
      ym = fmaxf(ym, __shfl_xor_sync(FULLMASK, ym, off));

    float thr = ym - 20.45f;  // gumbel spread <= 20.412
    unsigned m0 = __ballot_sync(FULLMASK, y0 >= thr);
    unsigned m1 = __ballot_sync(FULLMASK, has1 && (y1 >= thr));
    int mixidx;
    if (__popc(m0) + __popc(m1) == 1) {
      mixidx = m0 ? (__ffs(m0) - 1) : (__ffs(m1) + 31);
    } else {
      unsigned base = (unsigned)(gw * 6 + j) * 50u;
      float z = __int_as_float(0xFF800000);
      int zi = 64;
      if (y0 >= thr) { z = __fadd_rn(y0, gumbel_at(KMIX0, KMIX1, base + (unsigned)lane)); zi = lane; }
      if (has1 && y1 >= thr) {
        float z1 = __fadd_rn(y1, gumbel_at(KMIX0, KMIX1, base + (unsigned)t1));
        if (z1 > z) { z = z1; zi = t1; }
      }
#pragma unroll
      for (int off = 16; off > 0; off >>= 1) {
        float zo = __shfl_xor_sync(FULLMASK, z, off);
        int io = __shfl_xor_sync(FULLMASK, zi, off);
        if (zo > z || (zo == z && io < zi)) { z = zo; zi = io; }
      }
      mixidx = zi;
    }

    if (lane == 0) {
      float nrm = normal_at(KG0, KG1, (unsigned)(gw * 6 + j));
      float noise = __fmul_rn(nrm, 0.01f);
      out[(size_t)gw * 10 + 4 + j] =
          __fadd_rn(p[50 + mixidx], __fmul_rn(expf(p[100 + mixidx]), noise));
    }
  }
}

extern "C" void kernel_launch(void* const* d_in, const int* in_sizes, int n_in,
                              void* d_out, int out_size) {
  const float* A = (const float*)d_in[0];
  const float* W = (const float*)d_in[1];
  const float* bias = (const float*)d_in[2];
  float* out = (float*)d_out;

  // bn on x (fastest) so W + current A super-rows stay resident in L2
  dim3 ggrid((OUT_CH + BN - 1) / BN, SB / BM);  // (15, 816)
  gemm_kernel<<<ggrid, 128>>>(A, W, bias);
  sample_kernel<<<SB / 8, 256>>>(out);
}